// round 2
// baseline (speedup 1.0000x reference)
#include <cuda_runtime.h>

// GHM ranking loss, single streaming pass.
// Bins come from threshold compares on z (no sigmoid/exp needed):
//   g >= k/10  <=>  z > logit(k/10)
// Only bins 5..9 can carry loss (loss>0 => z>0 => g>0.5), so only
// cumulative counts/loss-sums at thresholds T5..T9 are needed.
// target is int32 (JAX downcasts int64 without x64 mode).

#define GHM_THREADS 256
#define GHM_BLOCKS  2048

static __device__ double             g_loss[5];  // L'_k = sum loss over {z > T_k}, k=5..9
static __device__ unsigned long long g_cnt[5];   // A_k  = #{z > T_k},             k=5..9

__global__ void ghm_init() {
    int i = threadIdx.x;
    if (i < 5) { g_loss[i] = 0.0; g_cnt[i] = 0ull; }
}

__global__ void __launch_bounds__(GHM_THREADS) ghm_main(
    const float4* __restrict__ o1,
    const float4* __restrict__ o2,
    const int4* __restrict__ tg,
    int nvec, int n)
{
    // logit(0.6..0.9)
    const float T6 = 0.40546510810816444f;
    const float T7 = 0.84729786038720363f;
    const float T8 = 1.38629436111989062f;
    const float T9 = 2.19722457733621939f;

    // Warp-aggregated counts (every lane holds the identical warp total,
    // accumulated from ballot popcounts)
    unsigned c5 = 0, c6 = 0, c7 = 0, c8 = 0, c9 = 0;
    // Tail-path per-lane counts (shuffle-reduced later; zero for N=2^24)
    unsigned ct5 = 0, ct6 = 0, ct7 = 0, ct8 = 0, ct9 = 0;
    // Per-lane loss partial sums (shuffle-reduced later)
    float l5 = 0.f, l6 = 0.f, l7 = 0.f, l8 = 0.f, l9 = 0.f;

    const int gtid = blockIdx.x * GHM_THREADS + threadIdx.x;
    const int tot  = gridDim.x * GHM_THREADS;
    const int full = nvec / tot;   // uniform trip count -> full-warp ballots

    #pragma unroll 2
    for (int k = 0; k < full; k++) {
        const int v = gtid + k * tot;
        const float4 a = o1[v];
        const float4 b = o2[v];
        const int4   t = tg[v];

        float av[4] = {a.x, a.y, a.z, a.w};
        float bv[4] = {b.x, b.y, b.z, b.w};
        int   tv[4] = {t.x, t.y, t.z, t.w};

        #pragma unroll
        for (int e = 0; e < 4; e++) {
            float d   = av[e] - bv[e];
            bool  t1  = (tv[e] != 0);
            float z   = t1 ? -d : d;                 // sigmoid argument
            float lz  = fmaxf(z, 0.f);
            float loss = t1 ? lz : 0.f;              // max(0, -t*diff)
            bool p5 = z > 0.f;
            bool p6 = z > T6;
            bool p7 = z > T7;
            bool p8 = z > T8;
            bool p9 = z > T9;
            l5 += loss;
            if (p6) l6 += loss;
            if (p7) l7 += loss;
            if (p8) l8 += loss;
            if (p9) l9 += loss;
            c5 += __popc(__ballot_sync(0xffffffffu, p5));
            c6 += __popc(__ballot_sync(0xffffffffu, p6));
            c7 += __popc(__ballot_sync(0xffffffffu, p7));
            c8 += __popc(__ballot_sync(0xffffffffu, p8));
            c9 += __popc(__ballot_sync(0xffffffffu, p9));
        }
    }

    // Vector tail (nvec not divisible by tot) — non-ballot path
    {
        const int v = gtid + full * tot;
        if (v < nvec) {
            const float4 a = o1[v];
            const float4 b = o2[v];
            const int4   t = tg[v];
            float av[4] = {a.x, a.y, a.z, a.w};
            float bv[4] = {b.x, b.y, b.z, b.w};
            int   tv[4] = {t.x, t.y, t.z, t.w};
            #pragma unroll
            for (int e = 0; e < 4; e++) {
                float d = av[e] - bv[e];
                bool t1 = (tv[e] != 0);
                float z = t1 ? -d : d;
                float loss = t1 ? fmaxf(z, 0.f) : 0.f;
                bool p5 = z > 0.f, p6 = z > T6, p7 = z > T7, p8 = z > T8, p9 = z > T9;
                l5 += loss;
                if (p6) l6 += loss;
                if (p7) l7 += loss;
                if (p8) l8 += loss;
                if (p9) l9 += loss;
                ct5 += p5; ct6 += p6; ct7 += p7; ct8 += p8; ct9 += p9;
            }
        }
    }
    // Scalar tail (n % 4)
    {
        const int idx = nvec * 4 + gtid;
        if (idx < n) {
            float d = ((const float*)o1)[idx] - ((const float*)o2)[idx];
            int   t = ((const int*)tg)[idx];
            bool t1 = (t != 0);
            float z = t1 ? -d : d;
            float loss = t1 ? fmaxf(z, 0.f) : 0.f;
            bool p5 = z > 0.f, p6 = z > T6, p7 = z > T7, p8 = z > T8, p9 = z > T9;
            l5 += loss;
            if (p6) l6 += loss;
            if (p7) l7 += loss;
            if (p8) l8 += loss;
            if (p9) l9 += loss;
            ct5 += p5; ct6 += p6; ct7 += p7; ct8 += p8; ct9 += p9;
        }
    }

    // Warp reduction: loss sums + tail counts (main counts already warp-uniform)
    #pragma unroll
    for (int off = 16; off > 0; off >>= 1) {
        l5 += __shfl_down_sync(0xffffffffu, l5, off);
        l6 += __shfl_down_sync(0xffffffffu, l6, off);
        l7 += __shfl_down_sync(0xffffffffu, l7, off);
        l8 += __shfl_down_sync(0xffffffffu, l8, off);
        l9 += __shfl_down_sync(0xffffffffu, l9, off);
        ct5 += __shfl_down_sync(0xffffffffu, ct5, off);
        ct6 += __shfl_down_sync(0xffffffffu, ct6, off);
        ct7 += __shfl_down_sync(0xffffffffu, ct7, off);
        ct8 += __shfl_down_sync(0xffffffffu, ct8, off);
        ct9 += __shfl_down_sync(0xffffffffu, ct9, off);
    }

    __shared__ float    sl[GHM_THREADS / 32][5];
    __shared__ unsigned sc[GHM_THREADS / 32][5];
    const int lane = threadIdx.x & 31;
    const int wrp  = threadIdx.x >> 5;
    if (lane == 0) {
        sl[wrp][0] = l5; sl[wrp][1] = l6; sl[wrp][2] = l7; sl[wrp][3] = l8; sl[wrp][4] = l9;
        sc[wrp][0] = c5 + ct5; sc[wrp][1] = c6 + ct6; sc[wrp][2] = c7 + ct7;
        sc[wrp][3] = c8 + ct8; sc[wrp][4] = c9 + ct9;
    }
    __syncthreads();
    if (threadIdx.x < 5) {
        float L = 0.f; unsigned C = 0u;
        #pragma unroll
        for (int i = 0; i < GHM_THREADS / 32; i++) {
            L += sl[i][threadIdx.x];
            C += sc[i][threadIdx.x];
        }
        atomicAdd(&g_loss[threadIdx.x], (double)L);
        atomicAdd(&g_cnt[threadIdx.x], (unsigned long long)C);
    }
}

__global__ void ghm_final(float* out, int n) {
    double A[5], L[5];
    #pragma unroll
    for (int i = 0; i < 5; i++) { A[i] = (double)g_cnt[i]; L[i] = g_loss[i]; }
    double res = 0.0;
    #pragma unroll
    for (int i = 0; i < 5; i++) {
        double C = A[i] - (i < 4 ? A[i + 1] : 0.0);  // count in bin 5+i
        double S = L[i] - (i < 4 ? L[i + 1] : 0.0);  // loss sum in bin 5+i
        if (C < 1.0) C = 1.0;
        res += pow(C, -0.75) * S;                    // w_b * S_b
    }
    out[0] = (float)(res / (double)n);
}

extern "C" void kernel_launch(void* const* d_in, const int* in_sizes, int n_in,
                              void* d_out, int out_size) {
    const float* o1 = (const float*)d_in[0];
    const float* o2 = (const float*)d_in[1];
    const int*   tg = (const int*)d_in[2];
    const int n = in_sizes[0];
    const int nvec = n >> 2;

    ghm_init<<<1, 32>>>();
    ghm_main<<<GHM_BLOCKS, GHM_THREADS>>>((const float4*)o1, (const float4*)o2,
                                          (const int4*)tg, nvec, n);
    ghm_final<<<1, 1>>>((float*)d_out, n);
}

// round 3
// speedup vs baseline: 1.0476x; 1.0476x over previous
#include <cuda_runtime.h>

// GHM ranking loss — single fused streaming kernel.
// Bins from threshold compares on z (no sigmoid):  g >= k/10  <=>  z > logit(k/10).
// Only bins 5..9 carry loss (loss>0 => z>0 => g>0.5): track cumulative counts
// A_k = #{z > T_k} and cumulative loss sums L'_k over thresholds T5..T9.
// Last-block-done pattern finalizes + resets state (graph-replay safe).

#define GHM_THREADS 256
#define GHM_BLOCKS  1024

static __device__ double             g_loss[5];
static __device__ unsigned long long g_cnt[5];
static __device__ unsigned int       g_done;

struct Acc {
    float    l5, l6, l7, l8, l9;
    unsigned c5, c6, c7, c8, c9;
};

__device__ __forceinline__ void ghm_elem(Acc& A, float a, float b, int t) {
    const float T6 = 0.40546510810816444f;   // logit(0.6)
    const float T7 = 0.84729786038720363f;   // logit(0.7)
    const float T8 = 1.38629436111989062f;   // logit(0.8)
    const float T9 = 2.19722457733621939f;   // logit(0.9)

    float d = a - b;
    int   s = t << 31;                                    // t in {0,1}
    float z = __int_as_float(__float_as_int(d) ^ s);      // z = t ? -d : d
    float loss = (t != 0) ? fmaxf(z, 0.f) : 0.f;          // max(0, -t*d)

    A.l5 += loss;
    if (z > 0.f) { A.c5++; }
    if (z > T6)  { A.c6++; A.l6 += loss; }
    if (z > T7)  { A.c7++; A.l7 += loss; }
    if (z > T8)  { A.c8++; A.l8 += loss; }
    if (z > T9)  { A.c9++; A.l9 += loss; }
}

__device__ __forceinline__ void ghm_vec(Acc& A, float4 a, float4 b, int4 t) {
    ghm_elem(A, a.x, b.x, t.x);
    ghm_elem(A, a.y, b.y, t.y);
    ghm_elem(A, a.z, b.z, t.z);
    ghm_elem(A, a.w, b.w, t.w);
}

__global__ void __launch_bounds__(GHM_THREADS) ghm_fused(
    const float4* __restrict__ o1,
    const float4* __restrict__ o2,
    const int4*   __restrict__ tg,
    float* __restrict__ out,
    int nvec, int n)
{
    Acc A = {0.f,0.f,0.f,0.f,0.f, 0u,0u,0u,0u,0u};

    const int gtid = blockIdx.x * GHM_THREADS + threadIdx.x;
    const int tot  = gridDim.x * GHM_THREADS;
    const int full = nvec / tot;

    // Main loop, 2 vector-iterations batched to double outstanding loads.
    int k = 0;
    for (; k + 2 <= full; k += 2) {
        const int v0 = gtid + k * tot;
        const int v1 = v0 + tot;
        float4 a0 = o1[v0], a1 = o1[v1];
        float4 b0 = o2[v0], b1 = o2[v1];
        int4   t0 = tg[v0], t1 = tg[v1];
        ghm_vec(A, a0, b0, t0);
        ghm_vec(A, a1, b1, t1);
    }
    for (; k < full; k++) {
        const int v = gtid + k * tot;
        ghm_vec(A, o1[v], o2[v], tg[v]);
    }
    // Vector tail
    {
        const int v = gtid + full * tot;
        if (v < nvec) ghm_vec(A, o1[v], o2[v], tg[v]);
    }
    // Scalar tail (n % 4)
    {
        const int idx = nvec * 4 + gtid;
        if (idx < n)
            ghm_elem(A, ((const float*)o1)[idx], ((const float*)o2)[idx],
                     ((const int*)tg)[idx]);
    }

    // Warp reduction
    #pragma unroll
    for (int off = 16; off > 0; off >>= 1) {
        A.l5 += __shfl_down_sync(0xffffffffu, A.l5, off);
        A.l6 += __shfl_down_sync(0xffffffffu, A.l6, off);
        A.l7 += __shfl_down_sync(0xffffffffu, A.l7, off);
        A.l8 += __shfl_down_sync(0xffffffffu, A.l8, off);
        A.l9 += __shfl_down_sync(0xffffffffu, A.l9, off);
        A.c5 += __shfl_down_sync(0xffffffffu, A.c5, off);
        A.c6 += __shfl_down_sync(0xffffffffu, A.c6, off);
        A.c7 += __shfl_down_sync(0xffffffffu, A.c7, off);
        A.c8 += __shfl_down_sync(0xffffffffu, A.c8, off);
        A.c9 += __shfl_down_sync(0xffffffffu, A.c9, off);
    }

    __shared__ float    sl[GHM_THREADS / 32][5];
    __shared__ unsigned sc[GHM_THREADS / 32][5];
    const int lane = threadIdx.x & 31;
    const int wrp  = threadIdx.x >> 5;
    if (lane == 0) {
        sl[wrp][0] = A.l5; sl[wrp][1] = A.l6; sl[wrp][2] = A.l7;
        sl[wrp][3] = A.l8; sl[wrp][4] = A.l9;
        sc[wrp][0] = A.c5; sc[wrp][1] = A.c6; sc[wrp][2] = A.c7;
        sc[wrp][3] = A.c8; sc[wrp][4] = A.c9;
    }
    __syncthreads();
    if (threadIdx.x < 5) {
        float L = 0.f; unsigned C = 0u;
        #pragma unroll
        for (int i = 0; i < GHM_THREADS / 32; i++) {
            L += sl[i][threadIdx.x];
            C += sc[i][threadIdx.x];
        }
        atomicAdd(&g_loss[threadIdx.x], (double)L);
        atomicAdd(&g_cnt[threadIdx.x], (unsigned long long)C);
    }
    __syncthreads();

    // Last block finalizes and resets state for the next graph replay.
    __shared__ bool s_last;
    if (threadIdx.x == 0) {
        __threadfence();
        unsigned done = atomicAdd(&g_done, 1u);
        s_last = (done == gridDim.x - 1);
    }
    __syncthreads();
    if (s_last && threadIdx.x == 0) {
        __threadfence();
        double Av[5], Lv[5];
        #pragma unroll
        for (int i = 0; i < 5; i++) {
            Av[i] = (double)g_cnt[i];
            Lv[i] = g_loss[i];
            g_cnt[i] = 0ull;
            g_loss[i] = 0.0;
        }
        g_done = 0u;
        double res = 0.0;
        #pragma unroll
        for (int i = 0; i < 5; i++) {
            double C = Av[i] - (i < 4 ? Av[i + 1] : 0.0);  // count in bin 5+i
            double S = Lv[i] - (i < 4 ? Lv[i + 1] : 0.0);  // loss sum in bin 5+i
            if (C < 1.0) C = 1.0;
            res += pow(C, -0.75) * S;
        }
        out[0] = (float)(res / (double)n);
    }
}

extern "C" void kernel_launch(void* const* d_in, const int* in_sizes, int n_in,
                              void* d_out, int out_size) {
    const float* o1 = (const float*)d_in[0];
    const float* o2 = (const float*)d_in[1];
    const int*   tg = (const int*)d_in[2];
    const int n = in_sizes[0];
    const int nvec = n >> 2;

    ghm_fused<<<GHM_BLOCKS, GHM_THREADS>>>((const float4*)o1, (const float4*)o2,
                                           (const int4*)tg, (float*)d_out, nvec, n);
}

// round 4
// speedup vs baseline: 1.0941x; 1.0443x over previous
#include <cuda_runtime.h>

// GHM ranking loss — single fused streaming kernel, packed f32x2 accumulation.
// Bins from threshold compares on z (no sigmoid): g >= k/10 <=> z > logit(k/10).
// Only bins 5..9 carry loss; track cumulative (count, loss-sum) pairs at
// thresholds T5..T9, each pair updated by ONE predicated add.rn.f32x2.
// Last-block-done finalize + state reset (graph-replay safe).

#define GHM_THREADS 256
#define GHM_BLOCKS  740   // 148 SMs x 5 resident blocks -> single balanced wave

static __device__ double       g_loss[5];
static __device__ double       g_cnt[5];
static __device__ unsigned int g_done;

// acc (64-bit pair: lo=count f32, hi=loss-sum f32) += val if z > T
__device__ __forceinline__ void acc_gt(unsigned long long& acc, float z, float T,
                                       unsigned long long val) {
    asm("{\n\t"
        ".reg .pred p;\n\t"
        "setp.gt.f32 p, %1, %2;\n\t"
        "@p add.rn.f32x2 %0, %0, %3;\n\t"
        "}"
        : "+l"(acc) : "f"(z), "f"(T), "l"(val));
}

__device__ __forceinline__ void packed_add(unsigned long long& acc, unsigned long long v) {
    asm("add.rn.f32x2 %0, %0, %1;" : "+l"(acc) : "l"(v));
}

__device__ __forceinline__ void ghm_elem(unsigned long long* acc, float a, float b, int t) {
    const float T6 = 0.40546510810816444f;   // logit(0.6)
    const float T7 = 0.84729786038720363f;   // logit(0.7)
    const float T8 = 1.38629436111989062f;   // logit(0.8)
    const float T9 = 2.19722457733621939f;   // logit(0.9)

    float d   = a - b;
    int mask  = -t;                                        // t in {0,1} -> 0 / all-ones
    int zi    = __float_as_int(d) ^ (mask & 0x80000000);   // z = t ? -d : d   (one LOP3)
    float z   = __int_as_float(zi);
    float loss = __int_as_float(zi & mask);                // t ? z : 0  (z>0 guard => max)

    unsigned long long val;
    asm("mov.b64 %0, {%1, %2};" : "=l"(val) : "f"(1.0f), "f"(loss));

    acc_gt(acc[0], z, 0.0f, val);
    acc_gt(acc[1], z, T6,   val);
    acc_gt(acc[2], z, T7,   val);
    acc_gt(acc[3], z, T8,   val);
    acc_gt(acc[4], z, T9,   val);
}

__device__ __forceinline__ void ghm_vec(unsigned long long* acc, float4 a, float4 b, int4 t) {
    ghm_elem(acc, a.x, b.x, t.x);
    ghm_elem(acc, a.y, b.y, t.y);
    ghm_elem(acc, a.z, b.z, t.z);
    ghm_elem(acc, a.w, b.w, t.w);
}

__global__ void __launch_bounds__(GHM_THREADS, 5) ghm_fused(
    const float4* __restrict__ o1,
    const float4* __restrict__ o2,
    const int4*   __restrict__ tg,
    float* __restrict__ out,
    int nvec, int n)
{
    unsigned long long acc[5] = {0ull, 0ull, 0ull, 0ull, 0ull};

    const int gtid = blockIdx.x * GHM_THREADS + threadIdx.x;
    const int tot  = gridDim.x * GHM_THREADS;
    const int full = nvec / tot;

    // Software-pipelined main loop: loads for iteration k+1 issue before
    // processing iteration k, keeping 3x128b loads in flight per warp.
    if (full > 0) {
        float4 a = o1[gtid];
        float4 b = o2[gtid];
        int4   t = tg[gtid];
        #pragma unroll 2
        for (int k = 1; k < full; k++) {
            const int v = gtid + k * tot;
            float4 an = o1[v];
            float4 bn = o2[v];
            int4   tn = tg[v];
            ghm_vec(acc, a, b, t);
            a = an; b = bn; t = tn;
        }
        ghm_vec(acc, a, b, t);
    }
    // Vector tail
    {
        const int v = gtid + full * tot;
        if (v < nvec) ghm_vec(acc, o1[v], o2[v], tg[v]);
    }
    // Scalar tail (n % 4)
    {
        const int idx = nvec * 4 + gtid;
        if (idx < n)
            ghm_elem(acc, ((const float*)o1)[idx], ((const float*)o2)[idx],
                     ((const int*)tg)[idx]);
    }

    // Warp reduction of packed (count, loss) pairs
    #pragma unroll
    for (int off = 16; off > 0; off >>= 1) {
        #pragma unroll
        for (int i = 0; i < 5; i++) {
            unsigned long long o = __shfl_down_sync(0xffffffffu, acc[i], off);
            packed_add(acc[i], o);
        }
    }

    __shared__ unsigned long long sp[GHM_THREADS / 32][5];
    const int lane = threadIdx.x & 31;
    const int wrp  = threadIdx.x >> 5;
    if (lane == 0) {
        #pragma unroll
        for (int i = 0; i < 5; i++) sp[wrp][i] = acc[i];
    }
    __syncthreads();
    if (threadIdx.x < 5) {
        unsigned long long s = sp[0][threadIdx.x];
        #pragma unroll
        for (int i = 1; i < GHM_THREADS / 32; i++) packed_add(s, sp[i][threadIdx.x]);
        float cf, lf;
        asm("mov.b64 {%0, %1}, %2;" : "=f"(cf), "=f"(lf) : "l"(s));
        atomicAdd(&g_cnt[threadIdx.x], (double)cf);
        atomicAdd(&g_loss[threadIdx.x], (double)lf);
    }
    __syncthreads();

    // Last block finalizes and resets state for the next graph replay.
    __shared__ bool s_last;
    if (threadIdx.x == 0) {
        __threadfence();
        unsigned done = atomicAdd(&g_done, 1u);
        s_last = (done == gridDim.x - 1);
    }
    __syncthreads();
    if (s_last && threadIdx.x == 0) {
        __threadfence();
        double Av[5], Lv[5];
        #pragma unroll
        for (int i = 0; i < 5; i++) {
            Av[i] = g_cnt[i];
            Lv[i] = g_loss[i];
            g_cnt[i] = 0.0;
            g_loss[i] = 0.0;
        }
        g_done = 0u;
        double res = 0.0;
        #pragma unroll
        for (int i = 0; i < 5; i++) {
            double C = Av[i] - (i < 4 ? Av[i + 1] : 0.0);  // count in bin 5+i
            double S = Lv[i] - (i < 4 ? Lv[i + 1] : 0.0);  // loss sum in bin 5+i
            if (C < 1.0) C = 1.0;
            res += pow(C, -0.75) * S;
        }
        out[0] = (float)(res / (double)n);
    }
}

extern "C" void kernel_launch(void* const* d_in, const int* in_sizes, int n_in,
                              void* d_out, int out_size) {
    const float* o1 = (const float*)d_in[0];
    const float* o2 = (const float*)d_in[1];
    const int*   tg = (const int*)d_in[2];
    const int n = in_sizes[0];
    const int nvec = n >> 2;

    ghm_fused<<<GHM_BLOCKS, GHM_THREADS>>>((const float4*)o1, (const float4*)o2,
                                           (const int4*)tg, (float*)d_out, nvec, n);
}

// round 5
// speedup vs baseline: 1.1314x; 1.0341x over previous
#include <cuda_runtime.h>

// GHM ranking loss — single fused streaming kernel.
// Bins via threshold compares on z (no sigmoid): g >= k/10 <=> z > logit(k/10).
// Only bins 5..9 carry loss. Per threshold k: r = FSET(z > Tk) in {0.0,1.0},
// cnt_k += r (FADD), loss_k += r*loss (FFMA). No predicates, no reg pairs.
// Last-block-done finalize + state reset (graph-replay safe).

#define GHM_THREADS 256
#define GHM_BLOCKS  888   // 148 SMs x 6 resident blocks

static __device__ double       g_loss[5];
static __device__ double       g_cnt[5];
static __device__ unsigned int g_done;

__device__ __forceinline__ float fset_gt(float z, float T) {
    float r;
    asm("set.gt.f32.f32 %0, %1, %2;" : "=f"(r) : "f"(z), "f"(T));
    return r;
}

struct Acc { float c[5]; float l[5]; };

__device__ __forceinline__ void ghm_elem(Acc& A, float a, float b, int t) {
    const float T6 = 0.40546510810816444f;   // logit(0.6)
    const float T7 = 0.84729786038720363f;   // logit(0.7)
    const float T8 = 1.38629436111989062f;   // logit(0.8)
    const float T9 = 2.19722457733621939f;   // logit(0.9)

    float d    = a - b;
    int   mask = -t;                                       // t in {0,1}
    int   zi   = __float_as_int(d) ^ (mask & 0x80000000);  // z = t ? -d : d (1 LOP3)
    float z    = __int_as_float(zi);
    float loss = __int_as_float(zi & mask);                // t ? z : 0 (sign handled by r)

    float r5 = fset_gt(z, 0.0f);
    float r6 = fset_gt(z, T6);
    float r7 = fset_gt(z, T7);
    float r8 = fset_gt(z, T8);
    float r9 = fset_gt(z, T9);

    A.c[0] += r5;  A.l[0] = fmaf(r5, loss, A.l[0]);
    A.c[1] += r6;  A.l[1] = fmaf(r6, loss, A.l[1]);
    A.c[2] += r7;  A.l[2] = fmaf(r7, loss, A.l[2]);
    A.c[3] += r8;  A.l[3] = fmaf(r8, loss, A.l[3]);
    A.c[4] += r9;  A.l[4] = fmaf(r9, loss, A.l[4]);
}

__device__ __forceinline__ void ghm_vec(Acc& A, float4 a, float4 b, int4 t) {
    ghm_elem(A, a.x, b.x, t.x);
    ghm_elem(A, a.y, b.y, t.y);
    ghm_elem(A, a.z, b.z, t.z);
    ghm_elem(A, a.w, b.w, t.w);
}

__global__ void __launch_bounds__(GHM_THREADS, 6) ghm_fused(
    const float4* __restrict__ o1,
    const float4* __restrict__ o2,
    const int4*   __restrict__ tg,
    float* __restrict__ out,
    int nvec, int n)
{
    Acc A;
    #pragma unroll
    for (int i = 0; i < 5; i++) { A.c[i] = 0.f; A.l[i] = 0.f; }

    const int gtid = blockIdx.x * GHM_THREADS + threadIdx.x;
    const int tot  = gridDim.x * GHM_THREADS;
    const int full = nvec / tot;

    // Software-pipelined main loop: prefetch next iteration's 3x128b loads.
    if (full > 0) {
        float4 a = o1[gtid];
        float4 b = o2[gtid];
        int4   t = tg[gtid];
        #pragma unroll 2
        for (int k = 1; k < full; k++) {
            const int v = gtid + k * tot;
            float4 an = o1[v];
            float4 bn = o2[v];
            int4   tn = tg[v];
            ghm_vec(A, a, b, t);
            a = an; b = bn; t = tn;
        }
        ghm_vec(A, a, b, t);
    }
    // Vector tail
    {
        const int v = gtid + full * tot;
        if (v < nvec) ghm_vec(A, o1[v], o2[v], tg[v]);
    }
    // Scalar tail (n % 4)
    {
        const int idx = nvec * 4 + gtid;
        if (idx < n)
            ghm_elem(A, ((const float*)o1)[idx], ((const float*)o2)[idx],
                     ((const int*)tg)[idx]);
    }

    // Warp reduction (10 f32 values)
    #pragma unroll
    for (int off = 16; off > 0; off >>= 1) {
        #pragma unroll
        for (int i = 0; i < 5; i++) {
            A.c[i] += __shfl_down_sync(0xffffffffu, A.c[i], off);
            A.l[i] += __shfl_down_sync(0xffffffffu, A.l[i], off);
        }
    }

    __shared__ float sc[GHM_THREADS / 32][5];
    __shared__ float sl[GHM_THREADS / 32][5];
    const int lane = threadIdx.x & 31;
    const int wrp  = threadIdx.x >> 5;
    if (lane == 0) {
        #pragma unroll
        for (int i = 0; i < 5; i++) { sc[wrp][i] = A.c[i]; sl[wrp][i] = A.l[i]; }
    }
    __syncthreads();
    if (threadIdx.x < 5) {
        float C = 0.f, L = 0.f;
        #pragma unroll
        for (int i = 0; i < GHM_THREADS / 32; i++) {
            C += sc[i][threadIdx.x];
            L += sl[i][threadIdx.x];
        }
        atomicAdd(&g_cnt[threadIdx.x], (double)C);
        atomicAdd(&g_loss[threadIdx.x], (double)L);
    }
    __syncthreads();

    // Last block finalizes and resets state for the next graph replay.
    __shared__ bool s_last;
    if (threadIdx.x == 0) {
        __threadfence();
        unsigned done = atomicAdd(&g_done, 1u);
        s_last = (done == gridDim.x - 1);
    }
    __syncthreads();
    if (s_last && threadIdx.x == 0) {
        __threadfence();
        double Av[5], Lv[5];
        #pragma unroll
        for (int i = 0; i < 5; i++) {
            Av[i] = g_cnt[i];
            Lv[i] = g_loss[i];
            g_cnt[i] = 0.0;
            g_loss[i] = 0.0;
        }
        g_done = 0u;
        double res = 0.0;
        #pragma unroll
        for (int i = 0; i < 5; i++) {
            double C = Av[i] - (i < 4 ? Av[i + 1] : 0.0);  // count in bin 5+i
            double S = Lv[i] - (i < 4 ? Lv[i + 1] : 0.0);  // loss sum in bin 5+i
            if (C < 1.0) C = 1.0;
            res += pow(C, -0.75) * S;
        }
        out[0] = (float)(res / (double)n);
    }
}

extern "C" void kernel_launch(void* const* d_in, const int* in_sizes, int n_in,
                              void* d_out, int out_size) {
    const float* o1 = (const float*)d_in[0];
    const float* o2 = (const float*)d_in[1];
    const int*   tg = (const int*)d_in[2];
    const int n = in_sizes[0];
    const int nvec = n >> 2;

    ghm_fused<<<GHM_BLOCKS, GHM_THREADS>>>((const float4*)o1, (const float4*)o2,
                                           (const int4*)tg, (float*)d_out, nvec, n);
}